// round 6
// baseline (speedup 1.0000x reference)
#include <cuda_runtime.h>
#include <math.h>

#define GS   28
#define NB   128
#define NH   64
#define ND   4
#define G5   320
#define KK2  128
#define FCH  512
#define NOUT 10
#define NCH    8        // h columns per chunk
#define NCHK   8        // chunks per cell
#define NBLK  896       // 28 slots * 4 dirs * 8 chunks

// Recurrent state: [dir][row][col][batch][h]
__device__ float g_h[ND][GS][GS][NB][NH];
__device__ float g_c[ND][GS][GS][NB][NH];
__device__ float g_z1[NB][FCH];
__device__ unsigned g_gen;
__device__ unsigned g_cnt2;

typedef unsigned long long u64;

__device__ __forceinline__ void fma2(u64 &d, u64 a, u64 b) {
    asm("fma.rn.f32x2 %0, %1, %2, %0;" : "+l"(d) : "l"(a), "l"(b));
}
__device__ __forceinline__ void unpack2(u64 v, float &lo, float &hi) {
    asm("mov.b64 {%0, %1}, %2;" : "=f"(lo), "=f"(hi) : "l"(v));
}
__device__ __forceinline__ float sigf(float x) { return 1.0f / (1.0f + __expf(-x)); }
__device__ __forceinline__ float tanh_acc(float x) {
    float e = __expf(-2.0f * fabsf(x));
    float t = (1.0f - e) / (1.0f + e);
    return copysignf(t, x);
}

__global__ void init_kernel() {
    if (threadIdx.x == 0) { g_gen = 0u; g_cnt2 = 0u; }
}

// Sense-reversing grid barrier; all NBLK blocks resident (proof in header).
__device__ __forceinline__ void grid_barrier(int tid, unsigned gen) {
    __threadfence();
    __syncthreads();
    if (tid == 0) {
        if (atomicAdd(&g_cnt2, 1u) == NBLK - 1u) {
            g_cnt2 = 0u;
            asm volatile("st.release.gpu.global.b32 [%0], %1;"
                         :: "l"(&g_gen), "r"(gen + 1u) : "memory");
        } else {
            unsigned v;
            do {
                __nanosleep(128);
                asm volatile("ld.acquire.gpu.global.b32 %0, [%1];"
                             : "=r"(v) : "l"(&g_gen) : "memory");
            } while (v == gen);
        }
    }
    __syncthreads();
    __threadfence();
}

// Persistent wavefront: one block per (diagonal-slot, dir, chunk8).
// blk decode: chunk = blk&7, dir = (blk>>3)&3, slot = blk>>5.
// 128 threads: tx = tid&7 (h in chunk), ty = tid>>3 (16 groups of 8 batch rows
// = 4 adjacent pairs) -> acc[4][5] packed f32x2.
__global__ __launch_bounds__(128, 7) void mdlstm_wave(
    const float* __restrict__ x,
    const float* __restrict__ Wx,
    const float* __restrict__ U,
    const float* __restrict__ bias)
{
    __shared__ __align__(16) float  As[32][130];   // [k][batch], transposed, padded
    __shared__ __align__(16) float2 Bs[32][40];    // U tile (5 gates x 8 h), duplicated
    __shared__ float xs[NB];

    int blk   = blockIdx.x;
    int chunk = blk & 7;
    int dir   = (blk >> 3) & 3;
    int slot  = blk >> 5;

    int tid = threadIdx.x;
    int tx  = tid & 7;
    int ty  = tid >> 3;           // 0..15
    int h0  = chunk * NCH;

    const float* Ud  = U    + dir * (KK2 * G5);
    const float* Wxd = Wx   + dir * G5;
    const float* bd  = bias + dir * G5;

    int hcol = h0 + tx;
    float wxb[5], bb[5];
    #pragma unroll
    for (int g = 0; g < 5; ++g) {
        wxb[g] = Wxd[g * 64 + hcol];
        bb[g]  = bd [g * 64 + hcol];
    }

    unsigned gen = 0u;

    for (int d = 0; d < 2 * GS - 1; ++d) {
        int rlo = d - (GS - 1); if (rlo < 0) rlo = 0;
        int k = d + 1;
        if (2 * GS - 1 - d < k) k = 2 * GS - 1 - d;
        if (k > GS) k = GS;

        if (slot < k) {
            int r = rlo + slot;
            int c = d - r;

            const float* hL = (c > 0) ? &g_h[dir][r][c-1][0][0] : nullptr;
            const float* hU = (r > 0) ? &g_h[dir][r-1][c][0][0] : nullptr;

            int rr = (dir & 2) ? (GS - 1 - r) : r;
            int cc = (dir & 1) ? (GS - 1 - c) : c;
            xs[tid] = x[tid * (GS * GS) + rr * GS + cc];

            u64 acc[4][5];
            #pragma unroll
            for (int p = 0; p < 4; ++p)
                #pragma unroll
                for (int g = 0; g < 5; ++g) acc[p][g] = 0ull;

            for (int kt = 0; kt < 4; ++kt) {
                const float* src  = (kt < 2) ? hL : hU;   // halves of [h_left, h_up]
                int kofs   = (kt & 1) * 32;
                int kglob0 = kt * 32;
                __syncthreads();
                // A tile (transposed): As[kk][b] = src[b*64 + kofs + kk]
                for (int i = tid; i < NB * 32; i += 128) {
                    int b  = i >> 5;
                    int kk = i & 31;
                    As[kk][b] = src ? src[b * NH + kofs + kk] : 0.0f;
                }
                // B tile: 32 x 40 (5 gates x 8 h of this chunk), duplicated
                for (int i = tid; i < 32 * 40; i += 128) {
                    int kk   = i / 40;
                    int col  = i % 40;
                    int gate = col >> 3;
                    int hh   = col & 7;
                    float v = Ud[(kglob0 + kk) * G5 + gate * 64 + h0 + hh];
                    Bs[kk][col] = make_float2(v, v);
                }
                __syncthreads();

                #pragma unroll 8
                for (int kk = 0; kk < 32; ++kk) {
                    u64 a[4], bf[5];
                    #pragma unroll
                    for (int p = 0; p < 4; ++p)
                        a[p] = *(const u64*)&As[kk][ty * 8 + 2 * p];
                    #pragma unroll
                    for (int g = 0; g < 5; ++g)
                        bf[g] = *(const u64*)&Bs[kk][g * 8 + tx];
                    #pragma unroll
                    for (int p = 0; p < 4; ++p)
                        #pragma unroll
                        for (int g = 0; g < 5; ++g)
                            fma2(acc[p][g], a[p], bf[g]);
                }
            }

            // Fused gate epilogue (c_left and c_up from global, R4-proven path)
            const float* cLp = (c > 0) ? &g_c[dir][r][c-1][0][0] : nullptr;
            const float* cUp = (r > 0) ? &g_c[dir][r-1][c][0][0] : nullptr;
            float* hOut = &g_h[dir][r][c][0][0];
            float* cOut = &g_c[dir][r][c][0][0];

            #pragma unroll
            for (int p = 0; p < 4; ++p) {
                int row0 = ty * 8 + 2 * p;
                float zl[5], zh[5];
                #pragma unroll
                for (int g = 0; g < 5; ++g) unpack2(acc[p][g], zl[g], zh[g]);
                #pragma unroll
                for (int half = 0; half < 2; ++half) {
                    int row = row0 + half;
                    float xv = xs[row];
                    float z0 = (half ? zh[0] : zl[0]) + xv * wxb[0] + bb[0]; // i
                    float z1 = (half ? zh[1] : zl[1]) + xv * wxb[1] + bb[1]; // f_left
                    float z2 = (half ? zh[2] : zl[2]) + xv * wxb[2] + bb[2]; // f_up
                    float z3 = (half ? zh[3] : zl[3]) + xv * wxb[3] + bb[3]; // o
                    float z4 = (half ? zh[4] : zl[4]) + xv * wxb[4] + bb[4]; // g
                    float cl = cLp ? cLp[row * NH + hcol] : 0.0f;
                    float cu = cUp ? cUp[row * NH + hcol] : 0.0f;
                    float cn = sigf(z0) * tanh_acc(z4) + sigf(z1) * cl + sigf(z2) * cu;
                    float hn = sigf(z3) * tanh_acc(cn);
                    cOut[row * NH + hcol] = cn;
                    hOut[row * NH + hcol] = hn;
                }
            }
        }

        grid_barrier(tid, gen);
        gen++;
    }
}

// z1 = relu(hfinal @ W1 + b1); hfinal[b][dir*64+h] = g_h[dir][27][27][b][h]
__global__ void head1_kernel(const float* __restrict__ W1,
                             const float* __restrict__ b1)
{
    __shared__ float a[ND * NH];
    int b = blockIdx.y;
    int n = blockIdx.x * 256 + threadIdx.x;
    {
        int dcol = threadIdx.x;
        int dir = dcol >> 6, hh = dcol & 63;
        a[dcol] = g_h[dir][GS - 1][GS - 1][b][hh];
    }
    __syncthreads();
    float acc = b1[n];
    #pragma unroll 8
    for (int k = 0; k < ND * NH; ++k)
        acc = fmaf(a[k], W1[k * FCH + n], acc);
    g_z1[b][n] = fmaxf(acc, 0.0f);
}

// out = softmax(z1 @ W2 + b2)
__global__ void head2_kernel(const float* __restrict__ W2,
                             const float* __restrict__ b2,
                             float* __restrict__ out)
{
    __shared__ float logit[NOUT];
    int b    = blockIdx.x;
    int tid  = threadIdx.x;        // 320 threads = 10 warps
    int w    = tid >> 5;
    int lane = tid & 31;
    float acc = 0.0f;
    for (int k = lane; k < FCH; k += 32)
        acc = fmaf(g_z1[b][k], W2[k * NOUT + w], acc);
    #pragma unroll
    for (int o = 16; o; o >>= 1)
        acc += __shfl_down_sync(0xffffffffu, acc, o);
    if (lane == 0) logit[w] = acc + b2[w];
    __syncthreads();
    if (tid == 0) {
        float m = -1e30f;
        #pragma unroll
        for (int j = 0; j < NOUT; ++j) m = fmaxf(m, logit[j]);
        float e[NOUT], s = 0.0f;
        #pragma unroll
        for (int j = 0; j < NOUT; ++j) { e[j] = __expf(logit[j] - m); s += e[j]; }
        float inv = 1.0f / s;
        #pragma unroll
        for (int j = 0; j < NOUT; ++j) out[b * NOUT + j] = e[j] * inv;
    }
}

extern "C" void kernel_launch(void* const* d_in, const int* in_sizes, int n_in,
                              void* d_out, int out_size)
{
    const float* x  = (const float*)d_in[0];
    const float* Wx = (const float*)d_in[1];
    const float* U  = (const float*)d_in[2];
    const float* bb = (const float*)d_in[3];
    const float* W1 = (const float*)d_in[4];
    const float* b1 = (const float*)d_in[5];
    const float* W2 = (const float*)d_in[6];
    const float* b2 = (const float*)d_in[7];
    float* out = (float*)d_out;

    init_kernel<<<1, 32>>>();
    mdlstm_wave<<<NBLK, 128>>>(x, Wx, U, bb);
    head1_kernel<<<dim3(2, NB), 256>>>(W1, b1);
    head2_kernel<<<NB, 320>>>(W2, b2, out);
}

// round 8
// speedup vs baseline: 1.0988x; 1.0988x over previous
#include <cuda_runtime.h>
#include <math.h>

#define GS   28
#define NB   128
#define NH   64
#define ND   4
#define G5   320
#define KK2  128
#define FCH  512
#define NOUT 10
#define NBLK      448     // 28 slots * 4 dirs * 4 chunk16
#define BLK_PER_DIR 112u

// dynamic smem layout (floats):
//   As[2][32][130]  : 2*4160  = 8320 floats  (A tiles, transposed, padded)
//   Bs[2][32][80]   : 2*2560  = 5120 floats  (U tiles, plain)
//   xs[128]         : 128 floats
#define AS_STRIDE 4160
#define BS_OFF    8320
#define BS_STRIDE 2560
#define XS_OFF    13440
#define SMEM_BYTES ((13440 + 128) * 4)   // 54272

// Recurrent state: [dir][row][col][batch][h]
__device__ float g_h[ND][GS][GS][NB][NH];
__device__ float g_c[ND][GS][GS][NB][NH];
__device__ float g_z1[NB][FCH];

struct __align__(128) Bar { unsigned gen; unsigned cnt; };
__device__ Bar g_bar[ND];

typedef unsigned long long u64;

__device__ __forceinline__ void fma2(u64 &d, u64 a, u64 b) {
    asm("fma.rn.f32x2 %0, %1, %2, %0;" : "+l"(d) : "l"(a), "l"(b));
}
__device__ __forceinline__ u64 dup2(float v) {
    u64 r; asm("mov.b64 %0, {%1, %1};" : "=l"(r) : "f"(v)); return r;
}
__device__ __forceinline__ void unpack2(u64 v, float &lo, float &hi) {
    asm("mov.b64 {%0, %1}, %2;" : "=f"(lo), "=f"(hi) : "l"(v));
}
__device__ __forceinline__ float sigf(float x) { return 1.0f / (1.0f + __expf(-x)); }
__device__ __forceinline__ float tanh_acc(float x) {
    float e = __expf(-2.0f * fabsf(x));
    float t = (1.0f - e) / (1.0f + e);
    return copysignf(t, x);
}

__global__ void init_kernel() {
    if (threadIdx.x < ND) { g_bar[threadIdx.x].gen = 0u; g_bar[threadIdx.x].cnt = 0u; }
}

// Per-dir sense-reversing barrier (R4-proven construct, 112 blocks per dir).
__device__ __forceinline__ void dir_barrier(int dir, int tid, unsigned gen) {
    __threadfence();
    __syncthreads();
    if (tid == 0) {
        if (atomicAdd(&g_bar[dir].cnt, 1u) == BLK_PER_DIR - 1u) {
            g_bar[dir].cnt = 0u;
            asm volatile("st.release.gpu.global.b32 [%0], %1;"
                         :: "l"(&g_bar[dir].gen), "r"(gen + 1u) : "memory");
        } else {
            unsigned v;
            do {
                asm volatile("ld.acquire.gpu.global.b32 %0, [%1];"
                             : "=r"(v) : "l"(&g_bar[dir].gen) : "memory");
            } while (v == gen);
        }
    }
    __syncthreads();
    __threadfence();
}

// Persistent wavefront: R4-verbatim math, double-buffered tiles, per-dir barrier.
// blk decode identical to R4: chunk = blk&3, dir = (blk>>2)&3, slot = blk>>4.
__global__ __launch_bounds__(128, 4) void mdlstm_wave(
    const float* __restrict__ x,
    const float* __restrict__ Wx,
    const float* __restrict__ U,
    const float* __restrict__ bias)
{
    extern __shared__ __align__(16) float smf[];

    int blk   = blockIdx.x;
    int chunk = blk & 3;
    int dir   = (blk >> 2) & 3;
    int slot  = blk >> 4;

    int tid = threadIdx.x;
    int tx  = tid & 15;
    int ty  = tid >> 4;           // 0..7
    int h0  = chunk * 16;

    const float* Ud  = U    + dir * (KK2 * G5);
    const float* Wxd = Wx   + dir * G5;
    const float* bd  = bias + dir * G5;

    int hcol = h0 + tx;
    float wxb[5], bb[5];
    #pragma unroll
    for (int g = 0; g < 5; ++g) {
        wxb[g] = Wxd[g * 64 + hcol];
        bb[g]  = bd [g * 64 + hcol];
    }

    unsigned gen = 0u;

    for (int d = 0; d < 2 * GS - 1; ++d) {
        int rlo = d - (GS - 1); if (rlo < 0) rlo = 0;
        int k = d + 1;
        if (2 * GS - 1 - d < k) k = 2 * GS - 1 - d;
        if (k > GS) k = GS;

        if (slot < k) {
            int r = rlo + slot;
            int c = d - r;

            const float* hL = (c > 0) ? &g_h[dir][r][c-1][0][0] : nullptr;
            const float* hU = (r > 0) ? &g_h[dir][r-1][c][0][0] : nullptr;

            int rr = (dir & 2) ? (GS - 1 - r) : r;
            int cc = (dir & 1) ? (GS - 1 - c) : c;
            smf[XS_OFF + tid] = x[tid * (GS * GS) + rr * GS + cc];

            u64 acc[8][5];
            #pragma unroll
            for (int p = 0; p < 8; ++p)
                #pragma unroll
                for (int g = 0; g < 5; ++g) acc[p][g] = 0ull;

            // ---- fill tile kt into buffer buf ----
            // (macro-free lambda-like block; kt in [0,4))
            #define FILL_TILE(buf, kt_)                                            \
            {                                                                       \
                const float* src  = ((kt_) < 2) ? hL : hU;                          \
                int kofs   = ((kt_) & 1) * 32;                                      \
                int kglob0 = (kt_) * 32;                                            \
                float* Ab = &smf[(buf) * AS_STRIDE];                                \
                float* Bb = &smf[BS_OFF + (buf) * BS_STRIDE];                       \
                _Pragma("unroll 4")                                                 \
                for (int i = tid; i < NB * 32; i += 128) {                          \
                    int b  = i >> 5;                                                \
                    int kk = i & 31;                                                \
                    Ab[kk * 130 + b] = src ? src[b * NH + kofs + kk] : 0.0f;        \
                }                                                                   \
                _Pragma("unroll 4")                                                 \
                for (int i = tid; i < 32 * 80; i += 128) {                          \
                    int kk   = i / 80;                                              \
                    int col  = i % 80;                                              \
                    int gate = col >> 4;                                            \
                    int hh   = col & 15;                                            \
                    Bb[kk * 80 + col] = Ud[(kglob0 + kk) * G5 + gate * 64 + h0 + hh];\
                }                                                                   \
            }

            FILL_TILE(0, 0)
            __syncthreads();

            #pragma unroll
            for (int kt = 0; kt < 4; ++kt) {
                if (kt < 3) FILL_TILE((kt + 1) & 1, kt + 1)

                const float* Ab = &smf[(kt & 1) * AS_STRIDE];
                const float* Bb = &smf[BS_OFF + (kt & 1) * BS_STRIDE];
                #pragma unroll 8
                for (int kk = 0; kk < 32; ++kk) {
                    u64 a[8], bf[5];
                    #pragma unroll
                    for (int p = 0; p < 8; ++p)
                        a[p] = *(const u64*)&Ab[kk * 130 + ty * 16 + 2 * p];
                    #pragma unroll
                    for (int g = 0; g < 5; ++g)
                        bf[g] = dup2(Bb[kk * 80 + g * 16 + tx]);
                    #pragma unroll
                    for (int p = 0; p < 8; ++p)
                        #pragma unroll
                        for (int g = 0; g < 5; ++g)
                            fma2(acc[p][g], a[p], bf[g]);
                }
                __syncthreads();
            }
            #undef FILL_TILE

            // Fused gate epilogue (R4 verbatim: c_left and c_up from global)
            const float* cLp = (c > 0) ? &g_c[dir][r][c-1][0][0] : nullptr;
            const float* cUp = (r > 0) ? &g_c[dir][r-1][c][0][0] : nullptr;
            float* hOut = &g_h[dir][r][c][0][0];
            float* cOut = &g_c[dir][r][c][0][0];

            #pragma unroll
            for (int p = 0; p < 8; ++p) {
                int row0 = ty * 16 + 2 * p;
                float zl[5], zh[5];
                #pragma unroll
                for (int g = 0; g < 5; ++g) unpack2(acc[p][g], zl[g], zh[g]);
                #pragma unroll
                for (int half = 0; half < 2; ++half) {
                    int row = row0 + half;
                    float xv = smf[XS_OFF + row];
                    float z0 = (half ? zh[0] : zl[0]) + xv * wxb[0] + bb[0]; // i
                    float z1 = (half ? zh[1] : zl[1]) + xv * wxb[1] + bb[1]; // f_left
                    float z2 = (half ? zh[2] : zl[2]) + xv * wxb[2] + bb[2]; // f_up
                    float z3 = (half ? zh[3] : zl[3]) + xv * wxb[3] + bb[3]; // o
                    float z4 = (half ? zh[4] : zl[4]) + xv * wxb[4] + bb[4]; // g
                    float cl = cLp ? cLp[row * NH + hcol] : 0.0f;
                    float cu = cUp ? cUp[row * NH + hcol] : 0.0f;
                    float cn = sigf(z0) * tanh_acc(z4) + sigf(z1) * cl + sigf(z2) * cu;
                    float hn = sigf(z3) * tanh_acc(cn);
                    cOut[row * NH + hcol] = cn;
                    hOut[row * NH + hcol] = hn;
                }
            }
        }

        dir_barrier(dir, tid, gen);
        gen++;
    }
}

// z1 = relu(hfinal @ W1 + b1); hfinal[b][dir*64+h] = g_h[dir][27][27][b][h]
__global__ void head1_kernel(const float* __restrict__ W1,
                             const float* __restrict__ b1)
{
    __shared__ float a[ND * NH];
    int b = blockIdx.y;
    int n = blockIdx.x * 256 + threadIdx.x;
    {
        int dcol = threadIdx.x;
        int dir = dcol >> 6, hh = dcol & 63;
        a[dcol] = g_h[dir][GS - 1][GS - 1][b][hh];
    }
    __syncthreads();
    float acc = b1[n];
    #pragma unroll 8
    for (int k = 0; k < ND * NH; ++k)
        acc = fmaf(a[k], W1[k * FCH + n], acc);
    g_z1[b][n] = fmaxf(acc, 0.0f);
}

// out = softmax(z1 @ W2 + b2)
__global__ void head2_kernel(const float* __restrict__ W2,
                             const float* __restrict__ b2,
                             float* __restrict__ out)
{
    __shared__ float logit[NOUT];
    int b    = blockIdx.x;
    int tid  = threadIdx.x;        // 320 threads = 10 warps
    int w    = tid >> 5;
    int lane = tid & 31;
    float acc = 0.0f;
    for (int k = lane; k < FCH; k += 32)
        acc = fmaf(g_z1[b][k], W2[k * NOUT + w], acc);
    #pragma unroll
    for (int o = 16; o; o >>= 1)
        acc += __shfl_down_sync(0xffffffffu, acc, o);
    if (lane == 0) logit[w] = acc + b2[w];
    __syncthreads();
    if (tid == 0) {
        float m = -1e30f;
        #pragma unroll
        for (int j = 0; j < NOUT; ++j) m = fmaxf(m, logit[j]);
        float e[NOUT], s = 0.0f;
        #pragma unroll
        for (int j = 0; j < NOUT; ++j) { e[j] = __expf(logit[j] - m); s += e[j]; }
        float inv = 1.0f / s;
        #pragma unroll
        for (int j = 0; j < NOUT; ++j) out[b * NOUT + j] = e[j] * inv;
    }
}

extern "C" void kernel_launch(void* const* d_in, const int* in_sizes, int n_in,
                              void* d_out, int out_size)
{
    const float* x  = (const float*)d_in[0];
    const float* Wx = (const float*)d_in[1];
    const float* U  = (const float*)d_in[2];
    const float* bb = (const float*)d_in[3];
    const float* W1 = (const float*)d_in[4];
    const float* b1 = (const float*)d_in[5];
    const float* W2 = (const float*)d_in[6];
    const float* b2 = (const float*)d_in[7];
    float* out = (float*)d_out;

    cudaFuncSetAttribute(mdlstm_wave,
                         cudaFuncAttributeMaxDynamicSharedMemorySize, SMEM_BYTES);

    init_kernel<<<1, 32>>>();
    mdlstm_wave<<<NBLK, 128, SMEM_BYTES>>>(x, Wx, U, bb);
    head1_kernel<<<dim3(2, NB), 256>>>(W1, b1);
    head2_kernel<<<NB, 320>>>(W2, b2, out);
}

// round 10
// speedup vs baseline: 1.4225x; 1.2946x over previous
#include <cuda_runtime.h>
#include <math.h>

#define GS   28
#define NB   128
#define NH   64
#define ND   4
#define G5   320
#define KK2  128
#define FCH  512
#define NOUT 10
#define NBLK      448     // 28 slots * 4 dirs * 4 chunk16
#define BLK_PER_DIR 112u

// dynamic smem layout (floats):
//   Us[128][80]   : 10240 floats (persistent U slice for this (dir,chunk))
//   As[2][8][130] :  2080 floats (A k-tiles of 8, transposed, padded, dbl-buf)
//   xs[128]       :   128 floats
#define US_SZ    10240
#define AS_OFF   10240
#define AS_TILE  1040          // 8*130
#define XS_OFF   (10240 + 2080)
#define SMEM_FLOATS (XS_OFF + 128)
#define SMEM_BYTES  (SMEM_FLOATS * 4)   // 49792

// Recurrent state: [dir][row][col][batch][h]
__device__ float g_h[ND][GS][GS][NB][NH];
__device__ float g_c[ND][GS][GS][NB][NH];
__device__ float g_z1[NB][FCH];

struct __align__(128) Bar { unsigned gen; unsigned cnt; };
__device__ Bar g_bar[ND];

typedef unsigned long long u64;

__device__ __forceinline__ void fma2(u64 &d, u64 a, u64 b) {
    asm("fma.rn.f32x2 %0, %1, %2, %0;" : "+l"(d) : "l"(a), "l"(b));
}
__device__ __forceinline__ u64 dup2(float v) {
    u64 r; asm("mov.b64 %0, {%1, %1};" : "=l"(r) : "f"(v)); return r;
}
__device__ __forceinline__ void unpack2(u64 v, float &lo, float &hi) {
    asm("mov.b64 {%0, %1}, %2;" : "=f"(lo), "=f"(hi) : "l"(v));
}
__device__ __forceinline__ float sigf(float x) { return 1.0f / (1.0f + __expf(-x)); }
__device__ __forceinline__ float tanh_acc(float x) {
    float e = __expf(-2.0f * fabsf(x));
    float t = (1.0f - e) / (1.0f + e);
    return copysignf(t, x);
}

__global__ void init_kernel() {
    if (threadIdx.x < ND) { g_bar[threadIdx.x].gen = 0u; g_bar[threadIdx.x].cnt = 0u; }
}

// Per-dir sense-reversing barrier (112 blocks per dir), nanosleep backoff
// (R4-proven primitive; hard spin removed -- it hammered L2).
__device__ __forceinline__ void dir_barrier(int dir, int tid, unsigned gen) {
    __threadfence();
    __syncthreads();
    if (tid == 0) {
        if (atomicAdd(&g_bar[dir].cnt, 1u) == BLK_PER_DIR - 1u) {
            g_bar[dir].cnt = 0u;
            asm volatile("st.release.gpu.global.b32 [%0], %1;"
                         :: "l"(&g_bar[dir].gen), "r"(gen + 1u) : "memory");
        } else {
            unsigned v;
            do {
                __nanosleep(64);
                asm volatile("ld.acquire.gpu.global.b32 %0, [%1];"
                             : "=r"(v) : "l"(&g_bar[dir].gen) : "memory");
            } while (v == gen);
        }
    }
    __syncthreads();
    __threadfence();
}

// Persistent wavefront: R4 partition + math, persistent-U smem, k8 dbl-buf A.
// blk decode identical to R4: chunk = blk&3, dir = (blk>>2)&3, slot = blk>>4.
__global__ __launch_bounds__(128, 4) void mdlstm_wave(
    const float* __restrict__ x,
    const float* __restrict__ Wx,
    const float* __restrict__ U,
    const float* __restrict__ bias)
{
    extern __shared__ __align__(16) float smf[];

    int blk   = blockIdx.x;
    int chunk = blk & 3;
    int dir   = (blk >> 2) & 3;
    int slot  = blk >> 4;

    int tid = threadIdx.x;
    int tx  = tid & 15;
    int ty  = tid >> 4;           // 0..7
    int h0  = chunk * 16;

    const float* Ud  = U    + dir * (KK2 * G5);
    const float* Wxd = Wx   + dir * G5;
    const float* bd  = bias + dir * G5;

    // ---- one-time: persistent U slice into smem ----
    // Us[kglob][col], col = gate*16 + hh  (same values R4 loaded per-cell)
    for (int i = tid; i < US_SZ; i += 128) {
        int kk   = i / 80;
        int col  = i - kk * 80;
        int gate = col >> 4;
        int hh   = col & 15;
        smf[i] = Ud[kk * G5 + gate * 64 + h0 + hh];
    }

    int hcol = h0 + tx;
    float wxb[5], bb[5];
    #pragma unroll
    for (int g = 0; g < 5; ++g) {
        wxb[g] = Wxd[g * 64 + hcol];
        bb[g]  = bd [g * 64 + hcol];
    }
    __syncthreads();

    unsigned gen = 0u;

    for (int d = 0; d < 2 * GS - 1; ++d) {
        int rlo = d - (GS - 1); if (rlo < 0) rlo = 0;
        int k = d + 1;
        if (2 * GS - 1 - d < k) k = 2 * GS - 1 - d;
        if (k > GS) k = GS;

        if (slot < k) {
            int r = rlo + slot;
            int c = d - r;

            const float* hL = (c > 0) ? &g_h[dir][r][c-1][0][0] : nullptr;
            const float* hU = (r > 0) ? &g_h[dir][r-1][c][0][0] : nullptr;

            int rr = (dir & 2) ? (GS - 1 - r) : r;
            int cc = (dir & 1) ? (GS - 1 - c) : c;
            smf[XS_OFF + tid] = x[tid * (GS * GS) + rr * GS + cc];

            u64 acc[8][5];
            #pragma unroll
            for (int p = 0; p < 8; ++p)
                #pragma unroll
                for (int g = 0; g < 5; ++g) acc[p][g] = 0ull;

            // A k-tile fill: tile t covers kglob = t*8 .. t*8+7
            // (t < 8 -> hL half, t >= 8 -> hU half; same k order as R4)
            #define FILL_A(buf, t_)                                            \
            {                                                                   \
                const float* src = ((t_) < 8) ? hL : hU;                        \
                int kofs = ((t_) & 7) * 8;                                      \
                float* Ab = &smf[AS_OFF + (buf) * AS_TILE];                     \
                _Pragma("unroll")                                               \
                for (int j = 0; j < 8; ++j) {                                   \
                    int i  = tid + j * 128;                                     \
                    int b  = i >> 3;                                            \
                    int kk = i & 7;                                             \
                    Ab[kk * 130 + b] = src ? src[b * NH + kofs + kk] : 0.0f;    \
                }                                                               \
            }

            FILL_A(0, 0)
            __syncthreads();

            #pragma unroll 4
            for (int t = 0; t < 16; ++t) {
                if (t < 15) FILL_A((t + 1) & 1, t + 1)

                const float* Ab = &smf[AS_OFF + (t & 1) * AS_TILE];
                const float* Ub = &smf[t * 8 * 80];
                #pragma unroll
                for (int kk = 0; kk < 8; ++kk) {
                    u64 a[8], bf[5];
                    #pragma unroll
                    for (int p = 0; p < 8; ++p)
                        a[p] = *(const u64*)&Ab[kk * 130 + ty * 16 + 2 * p];
                    #pragma unroll
                    for (int g = 0; g < 5; ++g)
                        bf[g] = dup2(Ub[kk * 80 + g * 16 + tx]);
                    #pragma unroll
                    for (int p = 0; p < 8; ++p)
                        #pragma unroll
                        for (int g = 0; g < 5; ++g)
                            fma2(acc[p][g], a[p], bf[g]);
                }
                __syncthreads();
            }
            #undef FILL_A

            // Fused gate epilogue (R4 verbatim: c_left and c_up from global)
            const float* cLp = (c > 0) ? &g_c[dir][r][c-1][0][0] : nullptr;
            const float* cUp = (r > 0) ? &g_c[dir][r-1][c][0][0] : nullptr;
            float* hOut = &g_h[dir][r][c][0][0];
            float* cOut = &g_c[dir][r][c][0][0];

            #pragma unroll
            for (int p = 0; p < 8; ++p) {
                int row0 = ty * 16 + 2 * p;
                float zl[5], zh[5];
                #pragma unroll
                for (int g = 0; g < 5; ++g) unpack2(acc[p][g], zl[g], zh[g]);
                #pragma unroll
                for (int half = 0; half < 2; ++half) {
                    int row = row0 + half;
                    float xv = smf[XS_OFF + row];
                    float z0 = (half ? zh[0] : zl[0]) + xv * wxb[0] + bb[0]; // i
                    float z1 = (half ? zh[1] : zl[1]) + xv * wxb[1] + bb[1]; // f_left
                    float z2 = (half ? zh[2] : zl[2]) + xv * wxb[2] + bb[2]; // f_up
                    float z3 = (half ? zh[3] : zl[3]) + xv * wxb[3] + bb[3]; // o
                    float z4 = (half ? zh[4] : zl[4]) + xv * wxb[4] + bb[4]; // g
                    float cl = cLp ? cLp[row * NH + hcol] : 0.0f;
                    float cu = cUp ? cUp[row * NH + hcol] : 0.0f;
                    float cn = sigf(z0) * tanh_acc(z4) + sigf(z1) * cl + sigf(z2) * cu;
                    float hn = sigf(z3) * tanh_acc(cn);
                    cOut[row * NH + hcol] = cn;
                    hOut[row * NH + hcol] = hn;
                }
            }
        }

        dir_barrier(dir, tid, gen);
        gen++;
    }
}

// z1 = relu(hfinal @ W1 + b1); hfinal[b][dir*64+h] = g_h[dir][27][27][b][h]
__global__ void head1_kernel(const float* __restrict__ W1,
                             const float* __restrict__ b1)
{
    __shared__ float a[ND * NH];
    int b = blockIdx.y;
    int n = blockIdx.x * 256 + threadIdx.x;
    {
        int dcol = threadIdx.x;
        int dir = dcol >> 6, hh = dcol & 63;
        a[dcol] = g_h[dir][GS - 1][GS - 1][b][hh];
    }
    __syncthreads();
    float acc = b1[n];
    #pragma unroll 8
    for (int k = 0; k < ND * NH; ++k)
        acc = fmaf(a[k], W1[k * FCH + n], acc);
    g_z1[b][n] = fmaxf(acc, 0.0f);
}

// out = softmax(z1 @ W2 + b2)
__global__ void head2_kernel(const float* __restrict__ W2,
                             const float* __restrict__ b2,
                             float* __restrict__ out)
{
    __shared__ float logit[NOUT];
    int b    = blockIdx.x;
    int tid  = threadIdx.x;        // 320 threads = 10 warps
    int w    = tid >> 5;
    int lane = tid & 31;
    float acc = 0.0f;
    for (int k = lane; k < FCH; k += 32)
        acc = fmaf(g_z1[b][k], W2[k * NOUT + w], acc);
    #pragma unroll
    for (int o = 16; o; o >>= 1)
        acc += __shfl_down_sync(0xffffffffu, acc, o);
    if (lane == 0) logit[w] = acc + b2[w];
    __syncthreads();
    if (tid == 0) {
        float m = -1e30f;
        #pragma unroll
        for (int j = 0; j < NOUT; ++j) m = fmaxf(m, logit[j]);
        float e[NOUT], s = 0.0f;
        #pragma unroll
        for (int j = 0; j < NOUT; ++j) { e[j] = __expf(logit[j] - m); s += e[j]; }
        float inv = 1.0f / s;
        #pragma unroll
        for (int j = 0; j < NOUT; ++j) out[b * NOUT + j] = e[j] * inv;
    }
}

extern "C" void kernel_launch(void* const* d_in, const int* in_sizes, int n_in,
                              void* d_out, int out_size)
{
    const float* x  = (const float*)d_in[0];
    const float* Wx = (const float*)d_in[1];
    const float* U  = (const float*)d_in[2];
    const float* bb = (const float*)d_in[3];
    const float* W1 = (const float*)d_in[4];
    const float* b1 = (const float*)d_in[5];
    const float* W2 = (const float*)d_in[6];
    const float* b2 = (const float*)d_in[7];
    float* out = (float*)d_out;

    cudaFuncSetAttribute(mdlstm_wave,
                         cudaFuncAttributeMaxDynamicSharedMemorySize, SMEM_BYTES);

    init_kernel<<<1, 32>>>();
    mdlstm_wave<<<NBLK, 128, SMEM_BYTES>>>(x, Wx, U, bb);
    head1_kernel<<<dim3(2, NB), 256>>>(W1, b1);
    head2_kernel<<<NB, 320>>>(W2, b2, out);
}